// round 10
// baseline (speedup 1.0000x reference)
#include <cuda_runtime.h>
#include <cuda_bf16.h>
#include <cstdint>

#define BB    8
#define TT_   384
#define HH    8
#define DH    64
#define CC    512
#define MROWS (BB*TT_)   // 3072 slots
#define NTOK  2048
#define KEFF  1024       // hi(512) | lo(512) per row
#define NIT   48         // 3 segments x 16 iters of BK=32
#define SEGMAX 192       // max tokens per ragged segment (binomial(384,1/40) tail ~0)

// ------------------------- scratch ------------------------------------------
__device__ __align__(256) __nv_bfloat16 g_xs[NTOK*KEFF];
__device__ __align__(256) __nv_bfloat16 g_ws[3*CC*KEFF];
__device__ __align__(256) __nv_bfloat16 g_wps[CC*KEFF];
__device__ __align__(256) __nv_bfloat16 g_ys[MROWS*KEFF];
__device__ float g_q0[NTOK*3*CC];     // [tok][q512|k512|v512]
__device__ int   g_lo[MROWS];
__device__ int   g_hi[MROWS];

// ------------------------- asm helpers --------------------------------------
__device__ __forceinline__ uint32_t smem_u32(const void* p) {
    uint32_t a;
    asm("{ .reg .u64 t; cvta.to.shared.u64 t, %1; cvt.u32.u64 %0, t; }" : "=r"(a) : "l"(p));
    return a;
}
#define MMA16816(d, a, b) \
    asm volatile("mma.sync.aligned.m16n8k16.row.col.f32.bf16.bf16.f32 " \
        "{%0,%1,%2,%3}, {%4,%5,%6,%7}, {%8,%9}, {%0,%1,%2,%3};" \
        : "+f"((d)[0]), "+f"((d)[1]), "+f"((d)[2]), "+f"((d)[3]) \
        : "r"((a)[0]), "r"((a)[1]), "r"((a)[2]), "r"((a)[3]), \
          "r"((b)[0]), "r"((b)[1]))
#define LDSM4(r0,r1,r2,r3,addr) \
    asm volatile("ldmatrix.sync.aligned.m8n8.x4.shared.b16 {%0,%1,%2,%3}, [%4];" \
        : "=r"(r0), "=r"(r1), "=r"(r2), "=r"(r3) : "r"(addr))
#define CPASYNC16(dst, src) \
    asm volatile("cp.async.cg.shared.global [%0], [%1], 16;" :: "r"(dst), "l"(src))
#define CPCOMMIT()  asm volatile("cp.async.commit_group;" ::: "memory")
#define CPWAIT2()   asm volatile("cp.async.wait_group 2;" ::: "memory")

// seg/k offsets for split passes: AhiBhi, AhiBlo, AloBhi
__device__ __forceinline__ void split_offs(int it, int& kA, int& kB) {
    int seg = it >> 4;
    kA = ((seg == 2) ? 512 : 0) + (it & 15) * 32;
    kB = ((seg == 1) ? 512 : 0) + (it & 15) * 32;
}

// ------------------------- fused conversion ---------------------------------
__device__ __forceinline__ void split4_store(float4 v, __nv_bfloat16* hi, __nv_bfloat16* lo) {
    __nv_bfloat16 h0 = __float2bfloat16(v.x), h1 = __float2bfloat16(v.y);
    __nv_bfloat16 h2 = __float2bfloat16(v.z), h3 = __float2bfloat16(v.w);
    __nv_bfloat16 l0 = __float2bfloat16(v.x - __bfloat162float(h0));
    __nv_bfloat16 l1 = __float2bfloat16(v.y - __bfloat162float(h1));
    __nv_bfloat16 l2 = __float2bfloat16(v.z - __bfloat162float(h2));
    __nv_bfloat16 l3 = __float2bfloat16(v.w - __bfloat162float(h3));
    __nv_bfloat162 H0, H1, L0, L1;
    H0.x = h0; H0.y = h1; H1.x = h2; H1.y = h3;
    L0.x = l0; L0.y = l1; L1.x = l2; L1.y = l3;
    uint2 uh, ul;
    uh.x = *reinterpret_cast<uint32_t*>(&H0); uh.y = *reinterpret_cast<uint32_t*>(&H1);
    ul.x = *reinterpret_cast<uint32_t*>(&L0); ul.y = *reinterpret_cast<uint32_t*>(&L1);
    *reinterpret_cast<uint2*>(hi) = uh;
    *reinterpret_cast<uint2*>(lo) = ul;
}

__global__ void conv_all(const float* __restrict__ x,
                         const float* __restrict__ Wq, const float* __restrict__ Wk,
                         const float* __restrict__ Wv, const float* __restrict__ Wp)
{
    int i = blockIdx.x * blockDim.x + threadIdx.x;   // (2048 + 4*512) * 128
    int m = i >> 7, f4 = i & 127;
    const float* src;
    __nv_bfloat16* dsthi;
    if (m < NTOK) {
        src = x + (size_t)m * CC;
        dsthi = g_xs + (size_t)m * KEFF;
    } else {
        int r = m - NTOK;
        int w = r >> 9, rr = r & 511;
        src = (w == 0 ? Wq : w == 1 ? Wk : w == 2 ? Wv : Wp) + (size_t)rr * CC;
        dsthi = (w < 3) ? g_ws + (size_t)(w * 512 + rr) * KEFF
                        : g_wps + (size_t)rr * KEFF;
    }
    float4 v = reinterpret_cast<const float4*>(src)[f4];
    split4_store(v, dsthi + f4 * 4, dsthi + 512 + f4 * 4);
}

// ------------------------- segment bounds -----------------------------------
__global__ void seg_kernel(const int* __restrict__ pb)
{
    int id = blockIdx.x * blockDim.x + threadIdx.x;
    if (id >= MROWS) return;
    int b = id / TT_, s = id % TT_;
    const int* row = pb + b * TT_;
    int v = row[s];
    int lo = s;     while (lo > 0   && row[lo-1] == v) lo--;
    int hi = s + 1; while (hi < TT_ && row[hi]   == v) hi++;
    g_lo[id] = lo;
    g_hi[id] = hi;
}

// ------------------------- QKV GEMM (128x128, 4-stage cp.async) -------------
#define ASTB 10240
#define QKV_SMEM (8*ASTB)

__global__ __launch_bounds__(256) void qkv_mma(
    const float* __restrict__ bq, const float* __restrict__ bk,
    const float* __restrict__ bv)
{
    extern __shared__ __align__(128) char smem[];
    const uint32_t sbA = smem_u32(smem);
    const uint32_t sbB = sbA + 4*ASTB;

    const int tid = threadIdx.x;
    const int lane = tid & 31, wid = tid >> 5;
    const int wm = wid >> 2, wn = wid & 3;
    const int m0 = blockIdx.x * 128, n0 = blockIdx.y * 128;

    const int crow = tid >> 1, cb = (tid & 1) * 16;
    const __nv_bfloat16* aG = g_xs + (size_t)(m0 + crow) * KEFF + cb;
    const __nv_bfloat16* bG = g_ws + (size_t)(n0 + crow) * KEFF + cb;
    const uint32_t dA = sbA + (uint32_t)(crow * 40 + cb) * 2;
    const uint32_t dB = sbB + (uint32_t)(crow * 40 + cb) * 2;

    float acc[4][4][4];
#pragma unroll
    for (int mi = 0; mi < 4; mi++)
#pragma unroll
        for (int nj = 0; nj < 4; nj++)
#pragma unroll
            for (int r = 0; r < 4; r++) acc[mi][nj][r] = 0.f;

#pragma unroll
    for (int p = 0; p < 3; p++) {
        int kA, kB; split_offs(p, kA, kB);
        uint32_t oA = dA + p*ASTB, oB = dB + p*ASTB;
        CPASYNC16(oA,      aG + kA);
        CPASYNC16(oA + 16, aG + kA + 8);
        CPASYNC16(oB,      bG + kB);
        CPASYNC16(oB + 16, bG + kB + 8);
        CPCOMMIT();
    }

    const uint32_t frow = (lane & 15), fcol = (lane >> 4) * 8;

    for (int it = 0; it < NIT; ++it) {
        CPWAIT2();
        __syncthreads();
        if (it + 3 < NIT) {
            int nst = it + 3, kA, kB; split_offs(nst, kA, kB);
            uint32_t oA = dA + (nst & 3)*ASTB, oB = dB + (nst & 3)*ASTB;
            CPASYNC16(oA,      aG + kA);
            CPASYNC16(oA + 16, aG + kA + 8);
            CPASYNC16(oB,      bG + kB);
            CPASYNC16(oB + 16, bG + kB + 8);
        }
        CPCOMMIT();

        const uint32_t aS = sbA + (it & 3)*ASTB;
        const uint32_t bS = sbB + (it & 3)*ASTB;
#pragma unroll
        for (int kk = 0; kk < 2; ++kk) {
            uint32_t af[4][4], br[2][4];
            const uint32_t cOff = (kk*16 + fcol) * 2;
#pragma unroll
            for (int mi = 0; mi < 4; mi++) {
                uint32_t ad = aS + (uint32_t)((wm*64 + mi*16 + frow) * 40) * 2 + cOff;
                LDSM4(af[mi][0], af[mi][1], af[mi][2], af[mi][3], ad);
            }
#pragma unroll
            for (int p = 0; p < 2; p++) {
                uint32_t bd = bS + (uint32_t)((wn*32 + p*16 + frow) * 40) * 2 + cOff;
                LDSM4(br[p][0], br[p][1], br[p][2], br[p][3], bd);
            }
#pragma unroll
            for (int mi = 0; mi < 4; mi++)
#pragma unroll
                for (int nj = 0; nj < 4; nj++) {
                    uint32_t bf[2] = { br[nj>>1][nj & 1], br[nj>>1][2 + (nj & 1)] };
                    MMA16816(acc[mi][nj], af[mi], bf);
                }
        }
    }

    const int mat = n0 >> 9;
    const float* bias = (mat == 0) ? bq : (mat == 1) ? bk : bv;
#pragma unroll
    for (int mi = 0; mi < 4; mi++) {
        int r = m0 + wm*64 + mi*16 + (lane >> 2);
#pragma unroll
        for (int nj = 0; nj < 4; nj++) {
            int cI = n0 + wn*32 + nj*8 + (lane & 3)*2;
            float b0v = bias[cI & 511], b1v = bias[(cI & 511) + 1];
            float2 v0 = { acc[mi][nj][0] + b0v, acc[mi][nj][1] + b1v };
            float2 v1 = { acc[mi][nj][2] + b0v, acc[mi][nj][3] + b1v };
            *reinterpret_cast<float2*>(g_q0 + (size_t)r * 1536 + cI)       = v0;
            *reinterpret_cast<float2*>(g_q0 + (size_t)(r + 8) * 1536 + cI) = v1;
        }
    }
}

// ------------------------- OUT GEMM (64x128 tile) ---------------------------
#define ASTB64 5120
#define OUT_SMEM (4*ASTB64 + 4*ASTB)

__global__ __launch_bounds__(256) void out_mma(
    const float* __restrict__ bp, const int* __restrict__ inv,
    float* __restrict__ out)
{
    extern __shared__ __align__(128) char smem[];
    const uint32_t sbA = smem_u32(smem);
    const uint32_t sbB = sbA + 4*ASTB64;

    const int tid = threadIdx.x;
    const int lane = tid & 31, wid = tid >> 5;
    const int wm = wid >> 2, wn = wid & 3;
    const int m0 = blockIdx.x * 64, n0 = blockIdx.y * 128;

    const int arw = tid >> 2, acb = (tid & 3) * 8;
    const __nv_bfloat16* aG = g_ys + (size_t)inv[m0 + arw] * KEFF + acb;
    const uint32_t dA = sbA + (uint32_t)(arw * 40 + acb) * 2;
    const int brw = tid >> 1, bcb = (tid & 1) * 16;
    const __nv_bfloat16* bG = g_wps + (size_t)(n0 + brw) * KEFF + bcb;
    const uint32_t dB = sbB + (uint32_t)(brw * 40 + bcb) * 2;

    float acc[2][4][4];
#pragma unroll
    for (int mi = 0; mi < 2; mi++)
#pragma unroll
        for (int nj = 0; nj < 4; nj++)
#pragma unroll
            for (int r = 0; r < 4; r++) acc[mi][nj][r] = 0.f;

#pragma unroll
    for (int p = 0; p < 3; p++) {
        int kA, kB; split_offs(p, kA, kB);
        CPASYNC16(dA + p*ASTB64, aG + kA);
        uint32_t oB = dB + p*ASTB;
        CPASYNC16(oB,      bG + kB);
        CPASYNC16(oB + 16, bG + kB + 8);
        CPCOMMIT();
    }

    const uint32_t frow = (lane & 15), fcol = (lane >> 4) * 8;

    for (int it = 0; it < NIT; ++it) {
        CPWAIT2();
        __syncthreads();
        if (it + 3 < NIT) {
            int nst = it + 3, kA, kB; split_offs(nst, kA, kB);
            CPASYNC16(dA + (nst & 3)*ASTB64, aG + kA);
            uint32_t oB = dB + (nst & 3)*ASTB;
            CPASYNC16(oB,      bG + kB);
            CPASYNC16(oB + 16, bG + kB + 8);
        }
        CPCOMMIT();

        const uint32_t aS = sbA + (it & 3)*ASTB64;
        const uint32_t bS = sbB + (it & 3)*ASTB;
#pragma unroll
        for (int kk = 0; kk < 2; ++kk) {
            uint32_t af[2][4], br[2][4];
            const uint32_t cOff = (kk*16 + fcol) * 2;
#pragma unroll
            for (int mi = 0; mi < 2; mi++) {
                uint32_t ad = aS + (uint32_t)((wm*32 + mi*16 + frow) * 40) * 2 + cOff;
                LDSM4(af[mi][0], af[mi][1], af[mi][2], af[mi][3], ad);
            }
#pragma unroll
            for (int p = 0; p < 2; p++) {
                uint32_t bd = bS + (uint32_t)((wn*32 + p*16 + frow) * 40) * 2 + cOff;
                LDSM4(br[p][0], br[p][1], br[p][2], br[p][3], bd);
            }
#pragma unroll
            for (int mi = 0; mi < 2; mi++)
#pragma unroll
                for (int nj = 0; nj < 4; nj++) {
                    uint32_t bf[2] = { br[nj>>1][nj & 1], br[nj>>1][2 + (nj & 1)] };
                    MMA16816(acc[mi][nj], af[mi], bf);
                }
        }
    }

#pragma unroll
    for (int mi = 0; mi < 2; mi++) {
        int r = m0 + wm*32 + mi*16 + (lane >> 2);
#pragma unroll
        for (int nj = 0; nj < 4; nj++) {
            int cI = n0 + wn*32 + nj*8 + (lane & 3)*2;
            float b0v = bp[cI], b1v = bp[cI + 1];
            float2 v0 = { acc[mi][nj][0] + b0v, acc[mi][nj][1] + b1v };
            float2 v1 = { acc[mi][nj][2] + b0v, acc[mi][nj][3] + b1v };
            *reinterpret_cast<float2*>(out + (size_t)r * CC + cI)       = v0;
            *reinterpret_cast<float2*>(out + (size_t)(r + 8) * CC + cI) = v1;
        }
    }
}

// ------------------------- attention (restructured) -------------------------
// CTA per (b,s). Phase1: thread-per-(h,t) float4 dot (no shuffles).
// Phase2: warp-per-2-heads softmax. Phase3: thread-per-(h,d4) coalesced AV.
__global__ __launch_bounds__(128) void attn_kernel(
    const float* __restrict__ relk, const float* __restrict__ relv,
    const int* __restrict__ pidx)
{
    const int id = blockIdx.x;              // b*T + s
    const int b  = id / TT_;
    const int lo = g_lo[id], L = g_hi[id] - lo;

    __shared__ float q_s[CC];               // 8 heads x 64
    __shared__ float p_s[HH][SEGMAX + 8];
    __shared__ float rinv_s[HH];
    __shared__ int   tok_sh[SEGMAX];

    const int tid = threadIdx.x, lane = tid & 31, w = tid >> 5;

    // load q row (512 floats = 128 float4, one per thread) + segment tokens
    reinterpret_cast<float4*>(q_s)[tid] =
        reinterpret_cast<const float4*>(g_q0 + (size_t)pidx[id] * 1536)[tid];
    for (int i = tid; i < L; i += 128) tok_sh[i] = pidx[b * TT_ + lo + i];
    __syncthreads();

    const size_t rbase = (size_t)id * TT_ * DH;

    // ---- phase 1: logits, thread per (h,t), full 64-dim float4 dot ----
    for (int idx = tid; idx < HH * L; idx += 128) {
        int h = idx / L, tt = idx - h * L;
        const float4* kp = reinterpret_cast<const float4*>(
            g_q0 + (size_t)tok_sh[tt] * 1536 + 512 + h * DH);
        const float4* rp = reinterpret_cast<const float4*>(
            relk + rbase + (size_t)(lo + tt) * DH);
        const float4* qp = reinterpret_cast<const float4*>(q_s + h * DH);
        float a0 = 0.f, a1 = 0.f, a2 = 0.f, a3 = 0.f;
#pragma unroll
        for (int d = 0; d < 16; d += 4) {
            float4 k0 = kp[d],   r0 = rp[d],   q0 = qp[d];
            float4 k1 = kp[d+1], r1 = rp[d+1], q1 = qp[d+1];
            float4 k2 = kp[d+2], r2 = rp[d+2], q2 = qp[d+2];
            float4 k3 = kp[d+3], r3 = rp[d+3], q3 = qp[d+3];
            a0 += q0.x*(k0.x+r0.x) + q0.y*(k0.y+r0.y) + q0.z*(k0.z+r0.z) + q0.w*(k0.w+r0.w);
            a1 += q1.x*(k1.x+r1.x) + q1.y*(k1.y+r1.y) + q1.z*(k1.z+r1.z) + q1.w*(k1.w+r1.w);
            a2 += q2.x*(k2.x+r2.x) + q2.y*(k2.y+r2.y) + q2.z*(k2.z+r2.z) + q2.w*(k2.w+r2.w);
            a3 += q3.x*(k3.x+r3.x) + q3.y*(k3.y+r3.y) + q3.z*(k3.z+r3.z) + q3.w*(k3.w+r3.w);
        }
        p_s[h][tt] = (a0 + a1 + a2 + a3) * 0.125f;   // 1/sqrt(64)
    }
    __syncthreads();

    // ---- phase 2: softmax, warp w owns heads 2w, 2w+1 ----
#pragma unroll
    for (int hh = 0; hh < 2; hh++) {
        int h = 2*w + hh;
        float m = -1e30f;
        for (int tt = lane; tt < L; tt += 32) m = fmaxf(m, p_s[h][tt]);
#pragma unroll
        for (int o = 16; o; o >>= 1) m = fmaxf(m, __shfl_xor_sync(0xffffffffu, m, o));
        float sum = 0.f;
        for (int tt = lane; tt < L; tt += 32) {
            float e = __expf(p_s[h][tt] - m);
            p_s[h][tt] = e;
            sum += e;
        }
#pragma unroll
        for (int o = 16; o; o >>= 1) sum += __shfl_xor_sync(0xffffffffu, sum, o);
        if (lane == 0) rinv_s[h] = 1.0f / sum;
    }
    __syncthreads();

    // ---- phase 3: AV, thread = (h, d4); coalesced v/relv float4 reads ----
    {
        const int h = tid >> 4, d4 = tid & 15;
        float4 acc = {0.f, 0.f, 0.f, 0.f};
        const float* ph = p_s[h];
#pragma unroll 2
        for (int tt = 0; tt < L; tt++) {
            float p = ph[tt];
            float4 v4 = *reinterpret_cast<const float4*>(
                g_q0 + (size_t)tok_sh[tt] * 1536 + 1024 + h * DH + d4 * 4);
            float4 r4 = *reinterpret_cast<const float4*>(
                relv + rbase + (size_t)(lo + tt) * DH + d4 * 4);
            acc.x += p * (v4.x + r4.x);
            acc.y += p * (v4.y + r4.y);
            acc.z += p * (v4.z + r4.z);
            acc.w += p * (v4.w + r4.w);
        }
        float rinv = rinv_s[h];
        float4 o4 = { acc.x*rinv, acc.y*rinv, acc.z*rinv, acc.w*rinv };
        size_t yb = (size_t)id * KEFF + h * DH + d4 * 4;
        split4_store(o4, g_ys + yb, g_ys + yb + 512);
    }
}

// ---------------------------------------------------------------------------
extern "C" void kernel_launch(void* const* d_in, const int* in_sizes, int n_in,
                              void* d_out, int out_size)
{
    const float* x    = (const float*)d_in[0];
    const float* relk = (const float*)d_in[1];
    const float* relv = (const float*)d_in[2];
    const float* Wq   = (const float*)d_in[3];
    const float* bq   = (const float*)d_in[4];
    const float* Wk   = (const float*)d_in[5];
    const float* bk   = (const float*)d_in[6];
    const float* Wv   = (const float*)d_in[7];
    const float* bv   = (const float*)d_in[8];
    const float* Wp   = (const float*)d_in[9];
    const float* bp   = (const float*)d_in[10];
    const int*   pidx = (const int*)d_in[11];
    const int*   pb   = (const int*)d_in[12];
    const int*   inv  = (const int*)d_in[13];
    float*       out  = (float*)d_out;

    cudaFuncSetAttribute(qkv_mma, cudaFuncAttributeMaxDynamicSharedMemorySize, QKV_SMEM);
    cudaFuncSetAttribute(out_mma, cudaFuncAttributeMaxDynamicSharedMemorySize, OUT_SMEM);

    conv_all<<<(NTOK + 4*CC) * 128 / 256, 256>>>(x, Wq, Wk, Wv, Wp);
    seg_kernel<<<(MROWS + 255) / 256, 256>>>(pb);
    qkv_mma<<<dim3(16, 12), 256, QKV_SMEM>>>(bq, bk, bv);
    attn_kernel<<<MROWS, 128>>>(relk, relv, pidx);
    out_mma<<<dim3(32, 4), 256, OUT_SMEM>>>(bp, inv, out);
}

// round 13
// speedup vs baseline: 1.1248x; 1.1248x over previous
#include <cuda_runtime.h>
#include <cuda_bf16.h>
#include <cstdint>

#define BB    8
#define TT_   384
#define HH    8
#define DH    64
#define CC    512
#define MROWS (BB*TT_)   // 3072 slots
#define NTOK  2048
#define KEFF  1024       // hi(512) | lo(512) per row
#define NIT   48         // 3 segments x 16 iters of BK=32
#define SEGMAX 192       // max tokens per ragged segment
#define SEGP   196       // padded stride: banks (4h+i) all distinct

// ------------------------- scratch ------------------------------------------
__device__ __align__(256) __nv_bfloat16 g_xs[NTOK*KEFF];
__device__ __align__(256) __nv_bfloat16 g_ws[3*CC*KEFF];
__device__ __align__(256) __nv_bfloat16 g_wps[CC*KEFF];
__device__ __align__(256) __nv_bfloat16 g_ys[MROWS*KEFF];
__device__ float g_q0[NTOK*3*CC];     // [tok][q512|k512|v512]
__device__ int   g_lo[MROWS];
__device__ int   g_hi[MROWS];

// ------------------------- asm helpers --------------------------------------
__device__ __forceinline__ uint32_t smem_u32(const void* p) {
    uint32_t a;
    asm("{ .reg .u64 t; cvta.to.shared.u64 t, %1; cvt.u32.u64 %0, t; }" : "=r"(a) : "l"(p));
    return a;
}
#define MMA16816(d, a, b) \
    asm volatile("mma.sync.aligned.m16n8k16.row.col.f32.bf16.bf16.f32 " \
        "{%0,%1,%2,%3}, {%4,%5,%6,%7}, {%8,%9}, {%0,%1,%2,%3};" \
        : "+f"((d)[0]), "+f"((d)[1]), "+f"((d)[2]), "+f"((d)[3]) \
        : "r"((a)[0]), "r"((a)[1]), "r"((a)[2]), "r"((a)[3]), \
          "r"((b)[0]), "r"((b)[1]))
#define LDSM4(r0,r1,r2,r3,addr) \
    asm volatile("ldmatrix.sync.aligned.m8n8.x4.shared.b16 {%0,%1,%2,%3}, [%4];" \
        : "=r"(r0), "=r"(r1), "=r"(r2), "=r"(r3) : "r"(addr))
#define CPASYNC16(dst, src) \
    asm volatile("cp.async.cg.shared.global [%0], [%1], 16;" :: "r"(dst), "l"(src))
#define CPCOMMIT()  asm volatile("cp.async.commit_group;" ::: "memory")
#define CPWAIT2()   asm volatile("cp.async.wait_group 2;" ::: "memory")

// seg/k offsets for split passes: AhiBhi, AhiBlo, AloBhi
__device__ __forceinline__ void split_offs(int it, int& kA, int& kB) {
    int seg = it >> 4;
    kA = ((seg == 2) ? 512 : 0) + (it & 15) * 32;
    kB = ((seg == 1) ? 512 : 0) + (it & 15) * 32;
}

// ------------------------- fused conversion ---------------------------------
__device__ __forceinline__ void split4_store(float4 v, __nv_bfloat16* hi, __nv_bfloat16* lo) {
    __nv_bfloat16 h0 = __float2bfloat16(v.x), h1 = __float2bfloat16(v.y);
    __nv_bfloat16 h2 = __float2bfloat16(v.z), h3 = __float2bfloat16(v.w);
    __nv_bfloat16 l0 = __float2bfloat16(v.x - __bfloat162float(h0));
    __nv_bfloat16 l1 = __float2bfloat16(v.y - __bfloat162float(h1));
    __nv_bfloat16 l2 = __float2bfloat16(v.z - __bfloat162float(h2));
    __nv_bfloat16 l3 = __float2bfloat16(v.w - __bfloat162float(h3));
    __nv_bfloat162 H0, H1, L0, L1;
    H0.x = h0; H0.y = h1; H1.x = h2; H1.y = h3;
    L0.x = l0; L0.y = l1; L1.x = l2; L1.y = l3;
    uint2 uh, ul;
    uh.x = *reinterpret_cast<uint32_t*>(&H0); uh.y = *reinterpret_cast<uint32_t*>(&H1);
    ul.x = *reinterpret_cast<uint32_t*>(&L0); ul.y = *reinterpret_cast<uint32_t*>(&L1);
    *reinterpret_cast<uint2*>(hi) = uh;
    *reinterpret_cast<uint2*>(lo) = ul;
}

__global__ void conv_all(const float* __restrict__ x,
                         const float* __restrict__ Wq, const float* __restrict__ Wk,
                         const float* __restrict__ Wv, const float* __restrict__ Wp)
{
    int i = blockIdx.x * blockDim.x + threadIdx.x;   // (2048 + 4*512) * 128
    int m = i >> 7, f4 = i & 127;
    const float* src;
    __nv_bfloat16* dsthi;
    if (m < NTOK) {
        src = x + (size_t)m * CC;
        dsthi = g_xs + (size_t)m * KEFF;
    } else {
        int r = m - NTOK;
        int w = r >> 9, rr = r & 511;
        src = (w == 0 ? Wq : w == 1 ? Wk : w == 2 ? Wv : Wp) + (size_t)rr * CC;
        dsthi = (w < 3) ? g_ws + (size_t)(w * 512 + rr) * KEFF
                        : g_wps + (size_t)rr * KEFF;
    }
    float4 v = reinterpret_cast<const float4*>(src)[f4];
    split4_store(v, dsthi + f4 * 4, dsthi + 512 + f4 * 4);
}

// ------------------------- segment bounds -----------------------------------
__global__ void seg_kernel(const int* __restrict__ pb)
{
    int id = blockIdx.x * blockDim.x + threadIdx.x;
    if (id >= MROWS) return;
    int b = id / TT_, s = id % TT_;
    const int* row = pb + b * TT_;
    int v = row[s];
    int lo = s;     while (lo > 0   && row[lo-1] == v) lo--;
    int hi = s + 1; while (hi < TT_ && row[hi]   == v) hi++;
    g_lo[id] = lo;
    g_hi[id] = hi;
}

// ------------------------- QKV GEMM (128x128, 4-stage cp.async) -------------
#define ASTB 10240
#define QKV_SMEM (8*ASTB)

__global__ __launch_bounds__(256) void qkv_mma(
    const float* __restrict__ bq, const float* __restrict__ bk,
    const float* __restrict__ bv)
{
    extern __shared__ __align__(128) char smem[];
    const uint32_t sbA = smem_u32(smem);
    const uint32_t sbB = sbA + 4*ASTB;

    const int tid = threadIdx.x;
    const int lane = tid & 31, wid = tid >> 5;
    const int wm = wid >> 2, wn = wid & 3;
    const int m0 = blockIdx.x * 128, n0 = blockIdx.y * 128;

    const int crow = tid >> 1, cb = (tid & 1) * 16;
    const __nv_bfloat16* aG = g_xs + (size_t)(m0 + crow) * KEFF + cb;
    const __nv_bfloat16* bG = g_ws + (size_t)(n0 + crow) * KEFF + cb;
    const uint32_t dA = sbA + (uint32_t)(crow * 40 + cb) * 2;
    const uint32_t dB = sbB + (uint32_t)(crow * 40 + cb) * 2;

    float acc[4][4][4];
#pragma unroll
    for (int mi = 0; mi < 4; mi++)
#pragma unroll
        for (int nj = 0; nj < 4; nj++)
#pragma unroll
            for (int r = 0; r < 4; r++) acc[mi][nj][r] = 0.f;

#pragma unroll
    for (int p = 0; p < 3; p++) {
        int kA, kB; split_offs(p, kA, kB);
        uint32_t oA = dA + p*ASTB, oB = dB + p*ASTB;
        CPASYNC16(oA,      aG + kA);
        CPASYNC16(oA + 16, aG + kA + 8);
        CPASYNC16(oB,      bG + kB);
        CPASYNC16(oB + 16, bG + kB + 8);
        CPCOMMIT();
    }

    const uint32_t frow = (lane & 15), fcol = (lane >> 4) * 8;

    for (int it = 0; it < NIT; ++it) {
        CPWAIT2();
        __syncthreads();
        if (it + 3 < NIT) {
            int nst = it + 3, kA, kB; split_offs(nst, kA, kB);
            uint32_t oA = dA + (nst & 3)*ASTB, oB = dB + (nst & 3)*ASTB;
            CPASYNC16(oA,      aG + kA);
            CPASYNC16(oA + 16, aG + kA + 8);
            CPASYNC16(oB,      bG + kB);
            CPASYNC16(oB + 16, bG + kB + 8);
        }
        CPCOMMIT();

        const uint32_t aS = sbA + (it & 3)*ASTB;
        const uint32_t bS = sbB + (it & 3)*ASTB;
#pragma unroll
        for (int kk = 0; kk < 2; ++kk) {
            uint32_t af[4][4], br[2][4];
            const uint32_t cOff = (kk*16 + fcol) * 2;
#pragma unroll
            for (int mi = 0; mi < 4; mi++) {
                uint32_t ad = aS + (uint32_t)((wm*64 + mi*16 + frow) * 40) * 2 + cOff;
                LDSM4(af[mi][0], af[mi][1], af[mi][2], af[mi][3], ad);
            }
#pragma unroll
            for (int p = 0; p < 2; p++) {
                uint32_t bd = bS + (uint32_t)((wn*32 + p*16 + frow) * 40) * 2 + cOff;
                LDSM4(br[p][0], br[p][1], br[p][2], br[p][3], bd);
            }
#pragma unroll
            for (int mi = 0; mi < 4; mi++)
#pragma unroll
                for (int nj = 0; nj < 4; nj++) {
                    uint32_t bf[2] = { br[nj>>1][nj & 1], br[nj>>1][2 + (nj & 1)] };
                    MMA16816(acc[mi][nj], af[mi], bf);
                }
        }
    }

    const int mat = n0 >> 9;
    const float* bias = (mat == 0) ? bq : (mat == 1) ? bk : bv;
#pragma unroll
    for (int mi = 0; mi < 4; mi++) {
        int r = m0 + wm*64 + mi*16 + (lane >> 2);
#pragma unroll
        for (int nj = 0; nj < 4; nj++) {
            int cI = n0 + wn*32 + nj*8 + (lane & 3)*2;
            float b0v = bias[cI & 511], b1v = bias[(cI & 511) + 1];
            float2 v0 = { acc[mi][nj][0] + b0v, acc[mi][nj][1] + b1v };
            float2 v1 = { acc[mi][nj][2] + b0v, acc[mi][nj][3] + b1v };
            *reinterpret_cast<float2*>(g_q0 + (size_t)r * 1536 + cI)       = v0;
            *reinterpret_cast<float2*>(g_q0 + (size_t)(r + 8) * 1536 + cI) = v1;
        }
    }
}

// ------------------------- OUT GEMM (64x128 tile) ---------------------------
#define ASTB64 5120
#define OUT_SMEM (4*ASTB64 + 4*ASTB)

__global__ __launch_bounds__(256) void out_mma(
    const float* __restrict__ bp, const int* __restrict__ inv,
    float* __restrict__ out)
{
    extern __shared__ __align__(128) char smem[];
    const uint32_t sbA = smem_u32(smem);
    const uint32_t sbB = sbA + 4*ASTB64;

    const int tid = threadIdx.x;
    const int lane = tid & 31, wid = tid >> 5;
    const int wm = wid >> 2, wn = wid & 3;
    const int m0 = blockIdx.x * 64, n0 = blockIdx.y * 128;

    const int arw = tid >> 2, acb = (tid & 3) * 8;
    const __nv_bfloat16* aG = g_ys + (size_t)inv[m0 + arw] * KEFF + acb;
    const uint32_t dA = sbA + (uint32_t)(arw * 40 + acb) * 2;
    const int brw = tid >> 1, bcb = (tid & 1) * 16;
    const __nv_bfloat16* bG = g_wps + (size_t)(n0 + brw) * KEFF + bcb;
    const uint32_t dB = sbB + (uint32_t)(brw * 40 + bcb) * 2;

    float acc[2][4][4];
#pragma unroll
    for (int mi = 0; mi < 2; mi++)
#pragma unroll
        for (int nj = 0; nj < 4; nj++)
#pragma unroll
            for (int r = 0; r < 4; r++) acc[mi][nj][r] = 0.f;

#pragma unroll
    for (int p = 0; p < 3; p++) {
        int kA, kB; split_offs(p, kA, kB);
        CPASYNC16(dA + p*ASTB64, aG + kA);
        uint32_t oB = dB + p*ASTB;
        CPASYNC16(oB,      bG + kB);
        CPASYNC16(oB + 16, bG + kB + 8);
        CPCOMMIT();
    }

    const uint32_t frow = (lane & 15), fcol = (lane >> 4) * 8;

    for (int it = 0; it < NIT; ++it) {
        CPWAIT2();
        __syncthreads();
        if (it + 3 < NIT) {
            int nst = it + 3, kA, kB; split_offs(nst, kA, kB);
            CPASYNC16(dA + (nst & 3)*ASTB64, aG + kA);
            uint32_t oB = dB + (nst & 3)*ASTB;
            CPASYNC16(oB,      bG + kB);
            CPASYNC16(oB + 16, bG + kB + 8);
        }
        CPCOMMIT();

        const uint32_t aS = sbA + (it & 3)*ASTB64;
        const uint32_t bS = sbB + (it & 3)*ASTB;
#pragma unroll
        for (int kk = 0; kk < 2; ++kk) {
            uint32_t af[2][4], br[2][4];
            const uint32_t cOff = (kk*16 + fcol) * 2;
#pragma unroll
            for (int mi = 0; mi < 2; mi++) {
                uint32_t ad = aS + (uint32_t)((wm*32 + mi*16 + frow) * 40) * 2 + cOff;
                LDSM4(af[mi][0], af[mi][1], af[mi][2], af[mi][3], ad);
            }
#pragma unroll
            for (int p = 0; p < 2; p++) {
                uint32_t bd = bS + (uint32_t)((wn*32 + p*16 + frow) * 40) * 2 + cOff;
                LDSM4(br[p][0], br[p][1], br[p][2], br[p][3], bd);
            }
#pragma unroll
            for (int mi = 0; mi < 2; mi++)
#pragma unroll
                for (int nj = 0; nj < 4; nj++) {
                    uint32_t bf[2] = { br[nj>>1][nj & 1], br[nj>>1][2 + (nj & 1)] };
                    MMA16816(acc[mi][nj], af[mi], bf);
                }
        }
    }

#pragma unroll
    for (int mi = 0; mi < 2; mi++) {
        int r = m0 + wm*32 + mi*16 + (lane >> 2);
#pragma unroll
        for (int nj = 0; nj < 4; nj++) {
            int cI = n0 + wn*32 + nj*8 + (lane & 3)*2;
            float b0v = bp[cI], b1v = bp[cI + 1];
            float2 v0 = { acc[mi][nj][0] + b0v, acc[mi][nj][1] + b1v };
            float2 v1 = { acc[mi][nj][2] + b0v, acc[mi][nj][3] + b1v };
            *reinterpret_cast<float2*>(out + (size_t)r * CC + cI)       = v0;
            *reinterpret_cast<float2*>(out + (size_t)(r + 8) * CC + cI) = v1;
        }
    }
}

// ------------------------- attention: warp per slot -------------------------
// lane = (h = lane>>2, chunk dq = (lane&3)*16). Warp covers the full 512-float
// k/v token row contiguously; relk/relv broadcast across head groups.
// No __syncthreads — 4 independent warps per CTA.
__global__ __launch_bounds__(128) void attn_kernel(
    const float* __restrict__ relk, const float* __restrict__ relv,
    const int* __restrict__ pidx)
{
    __shared__ float p_s[4][HH][SEGP];
    __shared__ int   tok_sh[4][SEGMAX];

    const int w    = threadIdx.x >> 5;
    const int lane = threadIdx.x & 31;
    const int id   = blockIdx.x * 4 + w;        // b*T + s
    const int b    = id / TT_;
    const int lo   = g_lo[id], L = g_hi[id] - lo;

    const int h  = lane >> 2;                   // 0..7
    const int g  = lane & 3;                    // 0..3 (16-dim chunk)
    const int dq = g * 16;

    // q fragment: 4 float4 = 16 dims
    const float4* qp = reinterpret_cast<const float4*>(
        g_q0 + (size_t)pidx[id] * 1536 + h * DH + dq);
    float4 q0 = qp[0], q1 = qp[1], q2 = qp[2], q3 = qp[3];

    for (int i = lane; i < L; i += 32) tok_sh[w][i] = pidx[b * TT_ + lo + i];
    __syncwarp();

    const size_t rbase = (size_t)id * TT_ * DH;

    // ---- phase 1: logits ----
    for (int t = 0; t < L; t++) {
        const float4* kp = reinterpret_cast<const float4*>(
            g_q0 + (size_t)tok_sh[w][t] * 1536 + 512 + h * DH + dq);
        const float4* rp = reinterpret_cast<const float4*>(
            relk + rbase + (size_t)(lo + t) * DH + dq);
        float4 k0 = kp[0], k1 = kp[1], k2 = kp[2], k3 = kp[3];
        float4 r0 = rp[0], r1 = rp[1], r2 = rp[2], r3 = rp[3];
        float a = q0.x*(k0.x+r0.x) + q0.y*(k0.y+r0.y) + q0.z*(k0.z+r0.z) + q0.w*(k0.w+r0.w)
                + q1.x*(k1.x+r1.x) + q1.y*(k1.y+r1.y) + q1.z*(k1.z+r1.z) + q1.w*(k1.w+r1.w)
                + q2.x*(k2.x+r2.x) + q2.y*(k2.y+r2.y) + q2.z*(k2.z+r2.z) + q2.w*(k2.w+r2.w)
                + q3.x*(k3.x+r3.x) + q3.y*(k3.y+r3.y) + q3.z*(k3.z+r3.z) + q3.w*(k3.w+r3.w);
        a += __shfl_xor_sync(0xffffffffu, a, 1);
        a += __shfl_xor_sync(0xffffffffu, a, 2);
        if (g == 0) p_s[w][h][t] = a * 0.125f;   // 1/sqrt(64)
    }
    __syncwarp();

    // ---- phase 2: softmax within each 4-lane head group ----
    float m = -1e30f;
    for (int t = g; t < L; t += 4) m = fmaxf(m, p_s[w][h][t]);
    m = fmaxf(m, __shfl_xor_sync(0xffffffffu, m, 1));
    m = fmaxf(m, __shfl_xor_sync(0xffffffffu, m, 2));
    float sum = 0.f;
    for (int t = g; t < L; t += 4) {
        float e = __expf(p_s[w][h][t] - m);
        p_s[w][h][t] = e;
        sum += e;
    }
    sum += __shfl_xor_sync(0xffffffffu, sum, 1);
    sum += __shfl_xor_sync(0xffffffffu, sum, 2);
    const float rinv = 1.0f / sum;
    __syncwarp();

    // ---- phase 3: AV ----
    float4 a0 = {0,0,0,0}, a1 = {0,0,0,0}, a2 = {0,0,0,0}, a3 = {0,0,0,0};
    for (int t = 0; t < L; t++) {
        float p = p_s[w][h][t];
        const float4* vp = reinterpret_cast<const float4*>(
            g_q0 + (size_t)tok_sh[w][t] * 1536 + 1024 + h * DH + dq);
        const float4* rp = reinterpret_cast<const float4*>(
            relv + rbase + (size_t)(lo + t) * DH + dq);
        float4 v0 = vp[0], v1 = vp[1], v2 = vp[2], v3 = vp[3];
        float4 r0 = rp[0], r1 = rp[1], r2 = rp[2], r3 = rp[3];
        a0.x += p*(v0.x+r0.x); a0.y += p*(v0.y+r0.y); a0.z += p*(v0.z+r0.z); a0.w += p*(v0.w+r0.w);
        a1.x += p*(v1.x+r1.x); a1.y += p*(v1.y+r1.y); a1.z += p*(v1.z+r1.z); a1.w += p*(v1.w+r1.w);
        a2.x += p*(v2.x+r2.x); a2.y += p*(v2.y+r2.y); a2.z += p*(v2.z+r2.z); a2.w += p*(v2.w+r2.w);
        a3.x += p*(v3.x+r3.x); a3.y += p*(v3.y+r3.y); a3.z += p*(v3.z+r3.z); a3.w += p*(v3.w+r3.w);
    }
    float4 o0 = {a0.x*rinv, a0.y*rinv, a0.z*rinv, a0.w*rinv};
    float4 o1 = {a1.x*rinv, a1.y*rinv, a1.z*rinv, a1.w*rinv};
    float4 o2 = {a2.x*rinv, a2.y*rinv, a2.z*rinv, a2.w*rinv};
    float4 o3 = {a3.x*rinv, a3.y*rinv, a3.z*rinv, a3.w*rinv};
    size_t yb = (size_t)id * KEFF + h * DH + dq;
    split4_store(o0, g_ys + yb,      g_ys + yb + 512);
    split4_store(o1, g_ys + yb + 4,  g_ys + yb + 516);
    split4_store(o2, g_ys + yb + 8,  g_ys + yb + 520);
    split4_store(o3, g_ys + yb + 12, g_ys + yb + 524);
}

// ---------------------------------------------------------------------------
extern "C" void kernel_launch(void* const* d_in, const int* in_sizes, int n_in,
                              void* d_out, int out_size)
{
    const float* x    = (const float*)d_in[0];
    const float* relk = (const float*)d_in[1];
    const float* relv = (const float*)d_in[2];
    const float* Wq   = (const float*)d_in[3];
    const float* bq   = (const float*)d_in[4];
    const float* Wk   = (const float*)d_in[5];
    const float* bk   = (const float*)d_in[6];
    const float* Wv   = (const float*)d_in[7];
    const float* bv   = (const float*)d_in[8];
    const float* Wp   = (const float*)d_in[9];
    const float* bp   = (const float*)d_in[10];
    const int*   pidx = (const int*)d_in[11];
    const int*   pb   = (const int*)d_in[12];
    const int*   inv  = (const int*)d_in[13];
    float*       out  = (float*)d_out;

    cudaFuncSetAttribute(qkv_mma, cudaFuncAttributeMaxDynamicSharedMemorySize, QKV_SMEM);
    cudaFuncSetAttribute(out_mma, cudaFuncAttributeMaxDynamicSharedMemorySize, OUT_SMEM);

    conv_all<<<(NTOK + 4*CC) * 128 / 256, 256>>>(x, Wq, Wk, Wv, Wp);
    seg_kernel<<<(MROWS + 255) / 256, 256>>>(pb);
    qkv_mma<<<dim3(16, 12), 256, QKV_SMEM>>>(bq, bk, bv);
    attn_kernel<<<MROWS / 4, 128>>>(relk, relv, pidx);
    out_mma<<<dim3(32, 4), 256, OUT_SMEM>>>(bp, inv, out);
}